// round 9
// baseline (speedup 1.0000x reference)
#include <cuda_runtime.h>
#include <cstdint>
#include <cstddef>

// Problem constants
#define BATCH   16
#define CIN     256
#define COUT    256
#define HW      64
#define KBANK   4
#define HIDDEN  65
#define TEMP    34.0f

// bank layout strides: weight[k][o][i][r][s]
#define BANK_K_STRIDE 589824   // 256*256*9
#define BANK_O_STRIDE 2304     // 256*9

// Conv tiling
#define ICCH   8                      // input-channel chunk
#define XROWS  18                     // 16 + 2 halo
#define XTILE  (ICCH * XROWS * XROWS) // 2592 floats
#define WSTR   65                     // padded oc stride (conflict-free smem writes)
#define WTILE  (ICCH * 9 * WSTR)      // 4680 floats

// Small intermediates (allocation-free scratch)
__device__ float g_pooled[BATCH * CIN];
__device__ float g_att[BATCH * KBANK];

// ---------------- f32x2 packed-FMA helpers (sm_100+) ----------------
__device__ __forceinline__ unsigned long long pack_f32x2(float lo, float hi) {
    unsigned long long r;
    asm("mov.b64 %0, {%1, %2};" : "=l"(r)
        : "r"(__float_as_uint(lo)), "r"(__float_as_uint(hi)));
    return r;
}
__device__ __forceinline__ void unpack_f32x2(unsigned long long v, float& lo, float& hi) {
    unsigned int a, b;
    asm("mov.b64 {%0, %1}, %2;" : "=r"(a), "=r"(b) : "l"(v));
    lo = __uint_as_float(a);
    hi = __uint_as_float(b);
}
__device__ __forceinline__ void fma_f32x2(unsigned long long& d,
                                          unsigned long long a,
                                          unsigned long long b) {
    asm("fma.rn.f32x2 %0, %1, %2, %0;" : "+l"(d) : "l"(a), "l"(b));
}

// ---------------- Kernel 1: global average pool -> g_pooled[b*256+c] ----------------
__global__ void pool_kernel(const float* __restrict__ x) {
    const int bc = blockIdx.x;                 // 0 .. 16*256-1
    const float* p = x + (size_t)bc * (HW * HW);
    float s = 0.f;
    for (int i = threadIdx.x; i < HW * HW; i += 256) s += p[i];
#pragma unroll
    for (int o = 16; o > 0; o >>= 1) s += __shfl_xor_sync(0xFFFFFFFFu, s, o);
    __shared__ float red[8];
    if ((threadIdx.x & 31) == 0) red[threadIdx.x >> 5] = s;
    __syncthreads();
    if (threadIdx.x == 0) {
        float t = 0.f;
#pragma unroll
        for (int w = 0; w < 8; w++) t += red[w];
        g_pooled[bc] = t * (1.0f / (HW * HW));
    }
}

// ---------------- Kernel 2: attention MLP + softmax -> g_att[b*4+k] ----------------
__global__ void att_kernel(const float* __restrict__ w1,   // [65,256]
                           const float* __restrict__ w2,   // [4,65]
                           const float* __restrict__ b2) { // [4]
    const int b = blockIdx.x;
    const int j = threadIdx.x;
    __shared__ float hs[HIDDEN];
    if (j < HIDDEN) {
        const float* pr = &g_pooled[b * CIN];
        const float* wr = &w1[j * CIN];
        float s = 0.f;
#pragma unroll 4
        for (int c = 0; c < CIN; c++) s += pr[c] * wr[c];
        hs[j] = fmaxf(s, 0.f);
    }
    __syncthreads();
    if (j == 0) {
        float lg[KBANK];
#pragma unroll
        for (int k = 0; k < KBANK; k++) {
            float s = b2[k];
            for (int h = 0; h < HIDDEN; h++) s += hs[h] * w2[k * HIDDEN + h];
            lg[k] = s * (1.0f / TEMP);
        }
        float m = lg[0];
#pragma unroll
        for (int k = 1; k < KBANK; k++) m = fmaxf(m, lg[k]);
        float e[KBANK];
        float Z = 0.f;
#pragma unroll
        for (int k = 0; k < KBANK; k++) { e[k] = expf(lg[k] - m); Z += e[k]; }
        float inv = 1.0f / Z;
#pragma unroll
        for (int k = 0; k < KBANK; k++) g_att[b * KBANK + k] = e[k] * inv;
    }
}

// ---------------- Kernel 3: per-sample dynamic conv (fused weight aggregation) ----
// Block: 64 out-ch x (16x16 pixel tile), 256 threads.
// Thread: 8 oc x 8 rows (1 col) = 64 accumulators as 32 f32x2 pairs.
// Warp = fixed oc group -> weight LDS are warp-uniform broadcasts.
// x smem row stride 18: half-warp row offset 8 -> 8*18 % 32 = 16 -> conflict-free.
__global__ __launch_bounds__(256, 2)
void conv_kernel(const float* __restrict__ x,
                 const float* __restrict__ bank,
                 float* __restrict__ out) {
    __shared__ float xs[XTILE];   // [ci][row18][col18]
    __shared__ float ws[WTILE];   // [(ci*9+rs)*65 + oc]

    const int b   = blockIdx.z;
    const int oc0 = blockIdx.y << 6;             // 0,64,128,192
    const int ty0 = (blockIdx.x >> 2) << 4;      // pixel tile origin
    const int tx0 = (blockIdx.x & 3) << 4;

    const int tid  = threadIdx.x;
    const int ocg  = tid >> 5;                   // 0..7 (warp id = oc group)
    const int lane = tid & 31;
    const int px   = lane & 15;                  // column within tile
    const int pyb  = (lane >> 4) << 3;           // row base: 0 or 8

    const float a0 = g_att[b * 4 + 0];
    const float a1 = g_att[b * 4 + 1];
    const float a2 = g_att[b * 4 + 2];
    const float a3 = g_att[b * 4 + 3];

    unsigned long long acc[8][4];
#pragma unroll
    for (int u = 0; u < 8; u++)
#pragma unroll
        for (int p = 0; p < 4; p++) acc[u][p] = 0ull;

    const float* xb = x + (size_t)b * (CIN * HW * HW);
    const float* wb = bank + (size_t)oc0 * BANK_O_STRIDE;

    for (int ic0 = 0; ic0 < CIN; ic0 += ICCH) {
        __syncthreads();
        // ---- stage x tile (with zero halo) ----
        for (int idx = tid; idx < XTILE; idx += 256) {
            int ci  = idx / (XROWS * XROWS);
            int rem = idx - ci * (XROWS * XROWS);
            int sy  = rem / XROWS;
            int sx  = rem - sy * XROWS;
            int gy  = ty0 - 1 + sy;
            int gx  = tx0 - 1 + sx;
            float v = 0.f;
            if ((unsigned)gy < (unsigned)HW && (unsigned)gx < (unsigned)HW)
                v = xb[(size_t)(ic0 + ci) * (HW * HW) + gy * HW + gx];
            xs[idx] = v;
        }
        // ---- stage weights with fused 4-bank aggregation (bank is L2-resident) ----
        for (int idx = tid; idx < 64 * (ICCH * 9); idx += 256) {
            int oc = idx / (ICCH * 9);
            int t  = idx - oc * (ICCH * 9);      // t = ci*9 + rs (contiguous in bank)
            const float* g = wb + (size_t)oc * BANK_O_STRIDE + ic0 * 9 + t;
            float w = a0 * g[0]
                    + a1 * g[BANK_K_STRIDE]
                    + a2 * g[2 * BANK_K_STRIDE]
                    + a3 * g[3 * BANK_K_STRIDE];
            ws[t * WSTR + oc] = w;
        }
        __syncthreads();

        // ---- compute ----
#pragma unroll
        for (int ci = 0; ci < ICCH; ci++) {
#pragma unroll
            for (int rs = 0; rs < 9; rs++) {
                const int r = rs / 3;
                const int s = rs - 3 * r;
                const float* xp = &xs[ci * (XROWS * XROWS) + (pyb + r) * XROWS + px + s];
                const float* wp = &ws[(ci * 9 + rs) * WSTR + (ocg << 3)];
                float xf[8];
#pragma unroll
                for (int j = 0; j < 8; j++) xf[j] = xp[j * XROWS];
                unsigned long long x2[4];
#pragma unroll
                for (int p = 0; p < 4; p++) x2[p] = pack_f32x2(xf[2 * p], xf[2 * p + 1]);
#pragma unroll
                for (int u = 0; u < 8; u++) {
                    float w = wp[u];
                    unsigned long long w2 = pack_f32x2(w, w);
#pragma unroll
                    for (int p = 0; p < 4; p++) fma_f32x2(acc[u][p], x2[p], w2);
                }
            }
        }
    }

    // ---- epilogue ----
    float* ob = out + ((size_t)(b * COUT + oc0 + (ocg << 3))) * (HW * HW)
                    + (ty0 + pyb) * HW + tx0 + px;
#pragma unroll
    for (int u = 0; u < 8; u++) {
#pragma unroll
        for (int p = 0; p < 4; p++) {
            float lo, hi;
            unpack_f32x2(acc[u][p], lo, hi);
            ob[u * (HW * HW) + (2 * p) * HW]     = lo;
            ob[u * (HW * HW) + (2 * p + 1) * HW] = hi;
        }
    }
}

// ---------------- launch ----------------
extern "C" void kernel_launch(void* const* d_in, const int* in_sizes, int n_in,
                              void* d_out, int out_size) {
    (void)in_sizes; (void)n_in; (void)out_size;
    const float* x    = (const float*)d_in[0];  // [16,256,64,64]
    const float* bank = (const float*)d_in[1];  // [4,256,256,3,3]
    const float* w1   = (const float*)d_in[2];  // [65,256]
    const float* w2   = (const float*)d_in[3];  // [4,65]
    const float* b2   = (const float*)d_in[4];  // [4]
    float* out = (float*)d_out;                 // [16,256,64,64]

    pool_kernel<<<BATCH * CIN, 256>>>(x);
    att_kernel<<<BATCH, 128>>>(w1, w2, b2);
    conv_kernel<<<dim3(16, 4, BATCH), 256>>>(x, bank, out);
}

// round 11
// speedup vs baseline: 2.9506x; 2.9506x over previous
#include <cuda_runtime.h>
#include <cstdint>
#include <cstddef>

// ---------------- problem constants ----------------
#define BATCH   16
#define CIN     256
#define COUT    256
#define HW      64
#define KBANK   4
#define HIDDEN  65
#define TEMP    34.0f
#define BANK_K_STRIDE (256*256*9)
#define BANK_O_STRIDE (256*9)

// ---------------- conv tiling ----------------
// CTA: 128 oc x 256 px (4 output rows). 8 warps = 2(M) x 4(N), warp tile 64x64.
// K = 2304 processed as 8 ci-chunks of 32 x 9 kernel shifts.
#define ASTR  36                 // A smem row stride (floats); 36 % 32 == 4 -> conflict-free frags
#define XRCI  424                // x-row cache ci stride (floats); 424 % 32 == 8 -> conflict-free
#define SM_A_BYTES  (128 * ASTR * 4)        // 18432
#define SM_XR_OFF   SM_A_BYTES
#define SM_TOTAL    (SM_XR_OFF + 32 * XRCI * 4)   // 18432 + 54272 = 72704

// ---------------- scratch (allocation-free) ----------------
__device__ float g_pooled[BATCH * CIN];
__device__ float g_att[BATCH * KBANK];
__device__ float g_aggw[BATCH * 9 * COUT * CIN];   // [b][rs][oc][ci], tf32-rounded

// ---------------- helpers ----------------
__device__ __forceinline__ uint32_t f2tf32(float f) {
    uint32_t u;
    asm("cvt.rna.tf32.f32 %0, %1;" : "=r"(u) : "f"(f));
    return u;
}

__device__ __forceinline__ void mma_tf32(float* d, const uint32_t* a, const uint32_t* b) {
    asm volatile(
        "mma.sync.aligned.m16n8k8.row.col.f32.tf32.tf32.f32 "
        "{%0,%1,%2,%3}, {%4,%5,%6,%7}, {%8,%9}, {%0,%1,%2,%3};"
        : "+f"(d[0]), "+f"(d[1]), "+f"(d[2]), "+f"(d[3])
        : "r"(a[0]), "r"(a[1]), "r"(a[2]), "r"(a[3]), "r"(b[0]), "r"(b[1]));
}

// ---------------- Kernel 1: global average pool ----------------
__global__ void pool_kernel(const float* __restrict__ x) {
    const int bc = blockIdx.x;
    const float4* p = (const float4*)(x + (size_t)bc * (HW * HW));
    float s = 0.f;
#pragma unroll 4
    for (int i = threadIdx.x; i < 1024; i += 256) {
        float4 v = p[i];
        s += (v.x + v.y) + (v.z + v.w);
    }
#pragma unroll
    for (int o = 16; o > 0; o >>= 1) s += __shfl_xor_sync(0xFFFFFFFFu, s, o);
    __shared__ float red[8];
    if ((threadIdx.x & 31) == 0) red[threadIdx.x >> 5] = s;
    __syncthreads();
    if (threadIdx.x == 0) {
        float t = 0.f;
#pragma unroll
        for (int w = 0; w < 8; w++) t += red[w];
        g_pooled[bc] = t * (1.0f / (HW * HW));
    }
}

// ---------------- Kernel 2: attention MLP + softmax ----------------
__global__ void att_kernel(const float* __restrict__ w1,
                           const float* __restrict__ w2,
                           const float* __restrict__ b2) {
    const int b = blockIdx.x;
    const int j = threadIdx.x;
    __shared__ float hs[HIDDEN];
    if (j < HIDDEN) {
        const float* pr = &g_pooled[b * CIN];
        const float* wr = &w1[j * CIN];
        float s = 0.f;
#pragma unroll 4
        for (int c = 0; c < CIN; c++) s += pr[c] * wr[c];
        hs[j] = fmaxf(s, 0.f);
    }
    __syncthreads();
    if (j == 0) {
        float lg[KBANK];
#pragma unroll
        for (int k = 0; k < KBANK; k++) {
            float s = b2[k];
            for (int h = 0; h < HIDDEN; h++) s += hs[h] * w2[k * HIDDEN + h];
            lg[k] = s * (1.0f / TEMP);
        }
        float m = lg[0];
#pragma unroll
        for (int k = 1; k < KBANK; k++) m = fmaxf(m, lg[k]);
        float e[KBANK], Z = 0.f;
#pragma unroll
        for (int k = 0; k < KBANK; k++) { e[k] = expf(lg[k] - m); Z += e[k]; }
        float inv = 1.0f / Z;
#pragma unroll
        for (int k = 0; k < KBANK; k++) g_att[b * KBANK + k] = e[k] * inv;
    }
}

// ---------------- Kernel 3: weight aggregation -> [b][rs][oc][ci], tf32-rounded ---
__global__ void agg_kernel(const float* __restrict__ bank) {
    const int oc = blockIdx.x;
    const int b  = blockIdx.y;
    const float a0 = g_att[b * 4 + 0], a1 = g_att[b * 4 + 1];
    const float a2 = g_att[b * 4 + 2], a3 = g_att[b * 4 + 3];
    const float* w = bank + (size_t)oc * BANK_O_STRIDE;
    uint32_t* dst = (uint32_t*)g_aggw + (size_t)b * 9 * 65536 + oc * 256;
    for (int t = threadIdx.x; t < 2304; t += 256) {
        float v = a0 * w[t] + a1 * w[t + BANK_K_STRIDE]
                + a2 * w[t + 2 * BANK_K_STRIDE] + a3 * w[t + 3 * BANK_K_STRIDE];
        int ci = t / 9;
        int rs = t - 9 * ci;
        dst[rs * 65536 + ci] = f2tf32(v);
    }
}

// ---------------- Kernel 4: tf32 mma.sync implicit-GEMM conv ----------------
__global__ __launch_bounds__(256, 1)
void conv_mma(const float* __restrict__ x, float* __restrict__ out) {
    extern __shared__ char smem[];
    float*    A_f  = (float*)smem;                  // [128][ASTR]
    uint32_t* A_u  = (uint32_t*)smem;
    uint32_t* xr   = (uint32_t*)(smem + SM_XR_OFF); // [32 ci][6 rows][68] stride XRCI

    const int tid  = threadIdx.x;
    const int wid  = tid >> 5;
    const int lane = tid & 31;
    const int g    = lane >> 2;      // group id (0..7)
    const int t    = lane & 3;       // thread in group (0..3)
    const int wm   = wid & 1;        // warp M tile (0..1)
    const int wn   = wid >> 1;       // warp N tile (0..3) == output row within CTA

    const int b   = blockIdx.z;
    const int oc0 = blockIdx.y << 7;
    const int y0  = blockIdx.x << 2; // 4 output rows per CTA

    const float* xb = x + (size_t)b * (CIN * HW * HW);
    const float* wb = g_aggw + (size_t)b * 9 * 65536;

    float acc[4][8][4];
#pragma unroll
    for (int mf = 0; mf < 4; mf++)
#pragma unroll
        for (int nf = 0; nf < 8; nf++)
#pragma unroll
            for (int k = 0; k < 4; k++) acc[mf][nf][k] = 0.f;

    // per-thread invariant bases
    const uint32_t* a_base = A_u + (wm * 64 + g) * ASTR + t;
    const uint32_t* x_base = xr + t * XRCI + wn * 68 + g;

    for (int chunk = 0; chunk < 8; chunk++) {
        const int ci0 = chunk * 32;
        __syncthreads();   // previous compute done reading xr
        // ---- stage x rows: 32 ci x 6 rows x cols -1..64 (tf32 rounded, zero halo) ----
        for (int q = tid; q < 32 * 6 * 16; q += 256) {
            int ci  = q / 96;
            int rem = q - ci * 96;
            int ri  = rem >> 4;
            int c4  = (rem & 15) << 2;
            int xrow = y0 - 1 + ri;
            float4 v = make_float4(0.f, 0.f, 0.f, 0.f);
            if ((unsigned)xrow < (unsigned)HW)
                v = *(const float4*)(xb + (size_t)(ci0 + ci) * (HW * HW) + xrow * HW + c4);
            uint32_t* d = xr + ci * XRCI + ri * 68 + 1 + c4;
            d[0] = f2tf32(v.x); d[1] = f2tf32(v.y); d[2] = f2tf32(v.z); d[3] = f2tf32(v.w);
        }
        if (tid < 192) {    // zero halo columns
            int ci = tid / 6, ri = tid - 6 * ci;
            uint32_t* d = xr + ci * XRCI + ri * 68;
            d[0] = 0u; d[65] = 0u;
        }

        for (int rs = 0; rs < 9; rs++) {
            __syncthreads();   // xr staged / previous A consumed
            // ---- stage A: 128 oc x 32 ci for this (rs, chunk) ----
            const float* arow = wb + (size_t)rs * 65536 + oc0 * 256 + ci0;
#pragma unroll
            for (int i = 0; i < 4; i++) {
                int q  = tid + i * 256;
                int m  = q >> 3;
                int kq = (q & 7) << 2;
                float4 v = *(const float4*)(arow + m * 256 + kq);
                float* dA = A_f + m * ASTR + kq;
                *(float2*)(dA)     = make_float2(v.x, v.y);
                *(float2*)(dA + 2) = make_float2(v.z, v.w);
            }
            __syncthreads();

            const int r = rs / 3, s = rs - 3 * r;
            const uint32_t* xs_ = x_base + r * 68 + s;
#pragma unroll
            for (int ks = 0; ks < 4; ks++) {
                const uint32_t* ap = a_base + ks * 8;
                uint32_t af[4][4];
#pragma unroll
                for (int mf = 0; mf < 4; mf++) {
                    const uint32_t* am = ap + mf * 16 * ASTR;
                    af[mf][0] = am[0];
                    af[mf][1] = am[8 * ASTR];
                    af[mf][2] = am[4];
                    af[mf][3] = am[8 * ASTR + 4];
                }
                const uint32_t* xp = xs_ + ks * 8 * XRCI;
                uint32_t bf[8][2];
#pragma unroll
                for (int nf = 0; nf < 8; nf++) {
                    bf[nf][0] = xp[nf * 8];
                    bf[nf][1] = xp[nf * 8 + 4 * XRCI];
                }
#pragma unroll
                for (int mf = 0; mf < 4; mf++)
#pragma unroll
                    for (int nf = 0; nf < 8; nf++)
                        mma_tf32(acc[mf][nf], af[mf], bf[nf]);
            }
        }
    }

    // ---- epilogue: D[m=16x8 frag] -> out[b][oc][y0+wn][px] ----
    const int ocr = oc0 + wm * 64 + g;
    const int yrow = (y0 + wn) * 64;
#pragma unroll
    for (int mf = 0; mf < 4; mf++) {
        float* o0 = out + ((size_t)(b * COUT + ocr + mf * 16)) * (HW * HW) + yrow;
        float* o1 = o0 + 8 * (HW * HW);
#pragma unroll
        for (int nf = 0; nf < 8; nf++) {
            int px0 = nf * 8 + 2 * t;
            *(float2*)(o0 + px0) = make_float2(acc[mf][nf][0], acc[mf][nf][1]);
            *(float2*)(o1 + px0) = make_float2(acc[mf][nf][2], acc[mf][nf][3]);
        }
    }
}

// ---------------- launch ----------------
extern "C" void kernel_launch(void* const* d_in, const int* in_sizes, int n_in,
                              void* d_out, int out_size) {
    (void)in_sizes; (void)n_in; (void)out_size;
    const float* x    = (const float*)d_in[0];  // [16,256,64,64]
    const float* bank = (const float*)d_in[1];  // [4,256,256,3,3]
    const float* w1   = (const float*)d_in[2];  // [65,256]
    const float* w2   = (const float*)d_in[3];  // [4,65]
    const float* b2   = (const float*)d_in[4];  // [4]
    float* out = (float*)d_out;                 // [16,256,64,64]

    static bool attr_set = false;
    if (!attr_set) {
        cudaFuncSetAttribute(conv_mma, cudaFuncAttributeMaxDynamicSharedMemorySize, SM_TOTAL);
        attr_set = true;
    }

    pool_kernel<<<BATCH * CIN, 256>>>(x);
    att_kernel<<<BATCH, 128>>>(w1, w2, b2);
    agg_kernel<<<dim3(COUT, BATCH), 256>>>(bank);
    conv_mma<<<dim3(16, 2, BATCH), 256, SM_TOTAL>>>(x, out);
}